// round 15
// baseline (speedup 1.0000x reference)
#include <cuda_runtime.h>
#include <cstdint>

#define CK_NSEQ 128
#define CK_NRES 256
#define CK_D    256
#define CK_P    128
#define CK_H    8
#define CK_C    32
#define CK_M    (CK_NSEQ * CK_NRES)   // 32768 rows

// ---------------------------------------------------------------------------
// Scratch (device globals -- no allocation allowed in kernel_launch)
// ---------------------------------------------------------------------------
__device__ float g_x   [CK_M * CK_D];            // LN(msa), tf32-rounded
__device__ float g_q   [CK_M * CK_D];            // [b,h,r,c], scaled, tf32
__device__ float g_k   [CK_M * CK_D];            // [b,h,r,c], tf32
__device__ float g_v   [CK_M * CK_D];            // [b,h,r,c], tf32
__device__ float g_gate[CK_M * CK_D];            // [b,r,h*c], sigmoid(.)
__device__ float g_o   [CK_M * CK_D];            // [b,r,h*c], gated attn out, tf32
__device__ float g_bias[CK_H * CK_NRES * CK_NRES]; // [h,q,k]

// ---------------------------------------------------------------------------
// Helpers
// ---------------------------------------------------------------------------
__device__ __forceinline__ float tf32r(float x) {
    unsigned u;
    asm("cvt.rna.tf32.f32 %0, %1;" : "=r"(u) : "f"(x));
    return __uint_as_float(u);
}
__device__ __forceinline__ unsigned fbits(float x) { return __float_as_uint(x); }

__device__ __forceinline__ void mma_tf32(float c[4], const unsigned a[4], const unsigned b[2]) {
    asm volatile(
        "mma.sync.aligned.m16n8k8.row.col.f32.tf32.tf32.f32 "
        "{%0,%1,%2,%3}, {%4,%5,%6,%7}, {%8,%9}, {%0,%1,%2,%3};"
        : "+f"(c[0]), "+f"(c[1]), "+f"(c[2]), "+f"(c[3])
        : "r"(a[0]), "r"(a[1]), "r"(a[2]), "r"(a[3]), "r"(b[0]), "r"(b[1]));
}

// ---------------------------------------------------------------------------
// Kernel A: LayerNorm over msa_act last dim (256). One block per row.
// ---------------------------------------------------------------------------
__global__ void __launch_bounds__(256) ln_msa_kernel(
    const float* __restrict__ x, const float* __restrict__ sc, const float* __restrict__ bi)
{
    const int row  = blockIdx.x;
    const int tid  = threadIdx.x;
    const int lane = tid & 31, w = tid >> 5;

    float v  = x[(size_t)row * 256 + tid];
    float s  = v, ss = v * v;
    #pragma unroll
    for (int off = 16; off > 0; off >>= 1) {
        s  += __shfl_xor_sync(0xffffffffu, s,  off);
        ss += __shfl_xor_sync(0xffffffffu, ss, off);
    }
    __shared__ float sm[16];
    if (lane == 0) { sm[w] = s; sm[8 + w] = ss; }
    __syncthreads();
    float tot = 0.f, tot2 = 0.f;
    #pragma unroll
    for (int i = 0; i < 8; i++) { tot += sm[i]; tot2 += sm[8 + i]; }
    float mu  = tot * (1.0f / 256.0f);
    float var = tot2 * (1.0f / 256.0f) - mu * mu;
    float rs  = rsqrtf(var + 1e-5f);
    g_x[(size_t)row * 256 + tid] = tf32r((v - mu) * rs * sc[tid] + bi[tid]);
}

// ---------------------------------------------------------------------------
// Kernel B: LN(pair) fused with bias[h,q,k] = sum_c pnorm[q,k,c] * feat2d_w[c,h].
// One warp per (q,k) pair; 128 channels = 4 per lane.
// ---------------------------------------------------------------------------
__global__ void __launch_bounds__(256) pair_bias_kernel(
    const float* __restrict__ pair, const float* __restrict__ ps,
    const float* __restrict__ pb,   const float* __restrict__ f2w)
{
    const int wg   = blockIdx.x * 8 + (threadIdx.x >> 5);
    const int lane = threadIdx.x & 31;
    const int q = wg >> 8, k = wg & 255;

    float4 v = reinterpret_cast<const float4*>(pair + (size_t)(q * 256 + k) * 128)[lane];
    float s  = v.x + v.y + v.z + v.w;
    float ss = v.x * v.x + v.y * v.y + v.z * v.z + v.w * v.w;
    #pragma unroll
    for (int off = 16; off > 0; off >>= 1) {
        s  += __shfl_xor_sync(0xffffffffu, s,  off);
        ss += __shfl_xor_sync(0xffffffffu, ss, off);
    }
    float mu  = s * (1.0f / 128.0f);
    float var = ss * (1.0f / 128.0f) - mu * mu;
    float rs  = rsqrtf(var + 1e-5f);

    float4 scv = reinterpret_cast<const float4*>(ps)[lane];
    float4 biv = reinterpret_cast<const float4*>(pb)[lane];
    float nv[4];
    nv[0] = (v.x - mu) * rs * scv.x + biv.x;
    nv[1] = (v.y - mu) * rs * scv.y + biv.y;
    nv[2] = (v.z - mu) * rs * scv.z + biv.z;
    nv[3] = (v.w - mu) * rs * scv.w + biv.w;

    float part[8] = {0, 0, 0, 0, 0, 0, 0, 0};
    const int c0 = lane * 4;
    #pragma unroll
    for (int j = 0; j < 4; j++) {
        const float* wr = f2w + (size_t)(c0 + j) * 8;
        float4 wa = reinterpret_cast<const float4*>(wr)[0];
        float4 wb = reinterpret_cast<const float4*>(wr)[1];
        float nj = nv[j];
        part[0] += nj * wa.x; part[1] += nj * wa.y; part[2] += nj * wa.z; part[3] += nj * wa.w;
        part[4] += nj * wb.x; part[5] += nj * wb.y; part[6] += nj * wb.z; part[7] += nj * wb.w;
    }
    #pragma unroll
    for (int hh = 0; hh < 8; hh++)
        #pragma unroll
        for (int off = 16; off > 0; off >>= 1)
            part[hh] += __shfl_xor_sync(0xffffffffu, part[hh], off);

    if (lane == 0) {
        #pragma unroll
        for (int hh = 0; hh < 8; hh++)
            g_bias[(size_t)hh * (CK_NRES * CK_NRES) + q * 256 + k] = part[hh];
    }
}

// ---------------------------------------------------------------------------
// GEMM (tf32 mma.sync m16n8k8): C[M,Ncols] = A[M,256] * W[256,Ncols]
// Block tile 128x128, BK=16, 8 warps (4x2), warp tile 32x64.
// MODE 0: A = g_x, four weight segments (Q,K,V,Gate) with custom epilogues.
// MODE 1: A = g_o, W = o_w, epilogue adds o_b and writes d_out.
// ---------------------------------------------------------------------------
template <int MODE>
__global__ void __launch_bounds__(256) gemm_kernel(
    const float* __restrict__ W0, const float* __restrict__ W1,
    const float* __restrict__ W2, const float* __restrict__ W3,
    const float* __restrict__ bias, float* __restrict__ out)
{
    const int bm = blockIdx.x, bn = blockIdx.y;
    const int tid = threadIdx.x;
    const int w = tid >> 5, lane = tid & 31;
    const int g = lane >> 2, t = lane & 3;
    const int wm = w >> 1, wn = w & 1;

    const float* A = (MODE == 0) ? g_x : g_o;
    const float* Bp;
    if (MODE == 0) {
        const int seg = bn >> 1;
        Bp = (seg == 0 ? W0 : seg == 1 ? W1 : seg == 2 ? W2 : W3) + (bn & 1) * 128;
    } else {
        Bp = W0 + bn * 128;
    }

    __shared__ float As[16][132];
    __shared__ float Bs[16][132];

    float c[2][8][4];
    #pragma unroll
    for (int i = 0; i < 2; i++)
        #pragma unroll
        for (int j = 0; j < 8; j++)
            #pragma unroll
            for (int r = 0; r < 4; r++) c[i][j][r] = 0.f;

    for (int kt = 0; kt < 16; ++kt) {
        const int k0 = kt * 16;
        #pragma unroll
        for (int i = 0; i < 2; i++) {
            int idx = tid + i * 256;
            int row = idx >> 2, f4 = idx & 3;
            float4 v = *reinterpret_cast<const float4*>(
                A + (size_t)(bm * 128 + row) * 256 + k0 + f4 * 4);
            As[f4 * 4 + 0][row] = v.x; As[f4 * 4 + 1][row] = v.y;
            As[f4 * 4 + 2][row] = v.z; As[f4 * 4 + 3][row] = v.w;
        }
        #pragma unroll
        for (int i = 0; i < 2; i++) {
            int idx = tid + i * 256;
            int row = idx >> 5, fc = idx & 31;
            float4 v = *reinterpret_cast<const float4*>(
                Bp + (size_t)(k0 + row) * 256 + fc * 4);
            Bs[row][fc * 4 + 0] = tf32r(v.x); Bs[row][fc * 4 + 1] = tf32r(v.y);
            Bs[row][fc * 4 + 2] = tf32r(v.z); Bs[row][fc * 4 + 3] = tf32r(v.w);
        }
        __syncthreads();

        #pragma unroll
        for (int ks = 0; ks < 2; ks++) {
            const int kk = ks * 8;
            unsigned a[2][4], bfr[8][2];
            #pragma unroll
            for (int mt = 0; mt < 2; mt++) {
                int m0 = wm * 32 + mt * 16 + g;
                a[mt][0] = fbits(As[kk + t][m0]);
                a[mt][1] = fbits(As[kk + t][m0 + 8]);
                a[mt][2] = fbits(As[kk + t + 4][m0]);
                a[mt][3] = fbits(As[kk + t + 4][m0 + 8]);
            }
            #pragma unroll
            for (int nt = 0; nt < 8; nt++) {
                int n0 = wn * 64 + nt * 8 + g;
                bfr[nt][0] = fbits(Bs[kk + t][n0]);
                bfr[nt][1] = fbits(Bs[kk + t + 4][n0]);
            }
            #pragma unroll
            for (int mt = 0; mt < 2; mt++)
                #pragma unroll
                for (int nt = 0; nt < 8; nt++)
                    mma_tf32(c[mt][nt], a[mt], bfr[nt]);
        }
        __syncthreads();
    }

    // Epilogue
    #pragma unroll
    for (int mt = 0; mt < 2; mt++)
        #pragma unroll
        for (int r2 = 0; r2 < 2; r2++) {
            const int grow = bm * 128 + wm * 32 + mt * 16 + r2 * 8 + g;
            const int b = grow >> 8, qr = grow & 255;
            #pragma unroll
            for (int nt = 0; nt < 8; nt++)
                #pragma unroll
                for (int j = 0; j < 2; j++) {
                    float val = c[mt][nt][r2 * 2 + j];
                    const int lcol = wn * 64 + nt * 8 + 2 * t + j;
                    if (MODE == 0) {
                        const int segcol = (bn & 1) * 128 + lcol;
                        const int seg = bn >> 1;
                        const int h = segcol >> 5, cc = segcol & 31;
                        const size_t qidx =
                            ((size_t)((b * CK_H + h) * CK_NRES + qr)) * CK_C + cc;
                        if (seg == 0)      g_q[qidx] = tf32r(val * 0.17677669529663687f);
                        else if (seg == 1) g_k[qidx] = tf32r(val);
                        else if (seg == 2) g_v[qidx] = tf32r(val);
                        else {
                            float z = val + bias[segcol];
                            g_gate[(size_t)grow * 256 + segcol] = 1.0f / (1.0f + __expf(-z));
                        }
                    } else {
                        const int gcol = bn * 128 + lcol;
                        out[(size_t)grow * 256 + gcol] = val + bias[gcol];
                    }
                }
        }
}

// ---------------------------------------------------------------------------
// Kernel D: attention per (b,h). 8 warps x 32 q-rows. Flash-style over K
// chunks of 64. S held in mma accumulators; P transposed C->A fragments via
// register shuffles (no smem round trip). Gating fused into epilogue.
// ---------------------------------------------------------------------------
__global__ void __launch_bounds__(256) attn_kernel(const float* __restrict__ mask)
{
    const int b = blockIdx.x, h = blockIdx.y;
    const int tid = threadIdx.x;
    const int lane = tid & 31, w = tid >> 5;
    const int g = lane >> 2, t = lane & 3;

    alignas(16) __shared__ float Ks[64][36];
    alignas(16) __shared__ float Vs[64][36];
    __shared__ float ms[256];

    ms[tid] = 1e9f * (mask[(size_t)b * 256 + tid] - 1.0f);

    const size_t bh = (size_t)(b * CK_H + h) * CK_NRES * CK_C;
    const float* Qb = g_q + bh;
    const float* Kb = g_k + bh;
    const float* Vb = g_v + bh;
    const float* biasb = g_bias + (size_t)h * (CK_NRES * CK_NRES);

    const int q0 = w * 32;

    // Q fragments (rows q0..q0+31, cols 0..31), held for all chunks
    unsigned aq[4][2][4];
    #pragma unroll
    for (int ks = 0; ks < 4; ks++)
        #pragma unroll
        for (int mt = 0; mt < 2; mt++) {
            int r0 = q0 + mt * 16 + g;
            aq[ks][mt][0] = fbits(Qb[(size_t)r0 * 32 + ks * 8 + t]);
            aq[ks][mt][1] = fbits(Qb[(size_t)(r0 + 8) * 32 + ks * 8 + t]);
            aq[ks][mt][2] = fbits(Qb[(size_t)r0 * 32 + ks * 8 + t + 4]);
            aq[ks][mt][3] = fbits(Qb[(size_t)(r0 + 8) * 32 + ks * 8 + t + 4]);
        }

    float o[2][4][4];
    #pragma unroll
    for (int i = 0; i < 2; i++)
        #pragma unroll
        for (int j = 0; j < 4; j++)
            #pragma unroll
            for (int r = 0; r < 4; r++) o[i][j][r] = 0.f;
    float mrow[2][2] = {{-1e30f, -1e30f}, {-1e30f, -1e30f}};
    float lrow[2][2] = {{0.f, 0.f}, {0.f, 0.f}};

    for (int ch = 0; ch < 4; ch++) {
        const int kb = ch * 64;
        __syncthreads();
        #pragma unroll
        for (int i = 0; i < 2; i++) {
            int idx = tid + i * 256;
            int row = idx >> 3, f4 = idx & 7;
            float4 kv = *reinterpret_cast<const float4*>(Kb + (size_t)(kb + row) * 32 + f4 * 4);
            *reinterpret_cast<float4*>(&Ks[row][f4 * 4]) = kv;
            float4 vv = *reinterpret_cast<const float4*>(Vb + (size_t)(kb + row) * 32 + f4 * 4);
            *reinterpret_cast<float4*>(&Vs[row][f4 * 4]) = vv;
        }
        __syncthreads();

        // S = Q * K^T (chunk 32 x 64)
        float s[2][8][4];
        #pragma unroll
        for (int i = 0; i < 2; i++)
            #pragma unroll
            for (int j = 0; j < 8; j++)
                #pragma unroll
                for (int r = 0; r < 4; r++) s[i][j][r] = 0.f;

        #pragma unroll
        for (int ks = 0; ks < 4; ks++) {
            unsigned bk[8][2];
            #pragma unroll
            for (int nt = 0; nt < 8; nt++) {
                bk[nt][0] = fbits(Ks[nt * 8 + g][ks * 8 + t]);
                bk[nt][1] = fbits(Ks[nt * 8 + g][ks * 8 + t + 4]);
            }
            #pragma unroll
            for (int mt = 0; mt < 2; mt++)
                #pragma unroll
                for (int nt = 0; nt < 8; nt++)
                    mma_tf32(s[mt][nt], aq[ks][mt], bk[nt]);
        }

        // bias + mask + online softmax
        #pragma unroll
        for (int mt = 0; mt < 2; mt++)
            #pragma unroll
            for (int rh = 0; rh < 2; rh++) {
                const int qr = q0 + mt * 16 + rh * 8 + g;
                const float* brow = biasb + (size_t)qr * 256 + kb;
                float mx = -1e30f;
                #pragma unroll
                for (int nt = 0; nt < 8; nt++)
                    #pragma unroll
                    for (int j = 0; j < 2; j++) {
                        int kc = nt * 8 + 2 * t + j;
                        float x = s[mt][nt][rh * 2 + j] + brow[kc] + ms[kb + kc];
                        s[mt][nt][rh * 2 + j] = x;
                        mx = fmaxf(mx, x);
                    }
                mx = fmaxf(mx, __shfl_xor_sync(0xffffffffu, mx, 1));
                mx = fmaxf(mx, __shfl_xor_sync(0xffffffffu, mx, 2));
                float nm   = fmaxf(mrow[mt][rh], mx);
                float corr = __expf(mrow[mt][rh] - nm);
                mrow[mt][rh] = nm;
                float rs = 0.f;
                #pragma unroll
                for (int nt = 0; nt < 8; nt++)
                    #pragma unroll
                    for (int j = 0; j < 2; j++) {
                        float p = __expf(s[mt][nt][rh * 2 + j] - nm);
                        s[mt][nt][rh * 2 + j] = p;
                        rs += p;
                    }
                rs += __shfl_xor_sync(0xffffffffu, rs, 1);
                rs += __shfl_xor_sync(0xffffffffu, rs, 2);
                lrow[mt][rh] = lrow[mt][rh] * corr + rs;
                #pragma unroll
                for (int nt = 0; nt < 4; nt++)
                    #pragma unroll
                    for (int j = 0; j < 2; j++)
                        o[mt][nt][rh * 2 + j] *= corr;
            }

        // O += P * V   (P: C-fragment -> A-fragment via shuffles)
        const int srcbase = lane & ~3;
        const int src0 = srcbase | (t >> 1);
        const int src1 = srcbase | ((t >> 1) + 2);
        const bool odd = (t & 1);
        #pragma unroll
        for (int ks = 0; ks < 8; ks++) {
            unsigned bv[4][2];
            #pragma unroll
            for (int nt = 0; nt < 4; nt++) {
                bv[nt][0] = fbits(Vs[ks * 8 + t][nt * 8 + g]);
                bv[nt][1] = fbits(Vs[ks * 8 + t + 4][nt * 8 + g]);
            }
            #pragma unroll
            for (int mt = 0; mt < 2; mt++) {
                unsigned pa[4];
                float lo, hi;
                lo = __shfl_sync(0xffffffffu, s[mt][ks][0], src0);
                hi = __shfl_sync(0xffffffffu, s[mt][ks][1], src0);
                pa[0] = fbits(tf32r(odd ? hi : lo));
                lo = __shfl_sync(0xffffffffu, s[mt][ks][2], src0);
                hi = __shfl_sync(0xffffffffu, s[mt][ks][3], src0);
                pa[1] = fbits(tf32r(odd ? hi : lo));
                lo = __shfl_sync(0xffffffffu, s[mt][ks][0], src1);
                hi = __shfl_sync(0xffffffffu, s[mt][ks][1], src1);
                pa[2] = fbits(tf32r(odd ? hi : lo));
                lo = __shfl_sync(0xffffffffu, s[mt][ks][2], src1);
                hi = __shfl_sync(0xffffffffu, s[mt][ks][3], src1);
                pa[3] = fbits(tf32r(odd ? hi : lo));
                #pragma unroll
                for (int nt = 0; nt < 4; nt++)
                    mma_tf32(o[mt][nt], pa, bv[nt]);
            }
        }
    }

    // finalize: normalize, gate, store (tf32-rounded for the output GEMM)
    #pragma unroll
    for (int mt = 0; mt < 2; mt++)
        #pragma unroll
        for (int rh = 0; rh < 2; rh++) {
            const float inv = 1.0f / lrow[mt][rh];
            const int qr = q0 + mt * 16 + rh * 8 + g;
            const size_t rowoff = ((size_t)(b * CK_NRES + qr)) * CK_D + h * CK_C;
            const float* gp = g_gate + rowoff;
            float* op = g_o + rowoff;
            #pragma unroll
            for (int nt = 0; nt < 4; nt++)
                #pragma unroll
                for (int j = 0; j < 2; j++) {
                    int cc = nt * 8 + 2 * t + j;
                    op[cc] = tf32r(o[mt][nt][rh * 2 + j] * inv * gp[cc]);
                }
        }
}

// ---------------------------------------------------------------------------
// Launch
// ---------------------------------------------------------------------------
extern "C" void kernel_launch(void* const* d_in, const int* in_sizes, int n_in,
                              void* d_out, int out_size)
{
    const float* msa  = (const float*)d_in[0];
    const float* mask = (const float*)d_in[1];
    const float* pair = (const float*)d_in[2];
    const float* qns  = (const float*)d_in[3];
    const float* qnb  = (const float*)d_in[4];
    const float* pns  = (const float*)d_in[5];
    const float* pnb  = (const float*)d_in[6];
    const float* f2w  = (const float*)d_in[7];
    const float* qw   = (const float*)d_in[8];
    const float* kw   = (const float*)d_in[9];
    const float* vw   = (const float*)d_in[10];
    const float* gw   = (const float*)d_in[11];
    const float* gatb = (const float*)d_in[12];
    const float* ow   = (const float*)d_in[13];
    const float* ob   = (const float*)d_in[14];
    float* out = (float*)d_out;

    ln_msa_kernel<<<CK_M, 256>>>(msa, qns, qnb);
    pair_bias_kernel<<<(CK_NRES * CK_NRES) / 8, 256>>>(pair, pns, pnb, f2w);
    gemm_kernel<0><<<dim3(CK_M / 128, 8), 256>>>(qw, kw, vw, gw, gatb, nullptr);
    attn_kernel<<<dim3(CK_NSEQ, CK_H), 256>>>(mask);
    gemm_kernel<1><<<dim3(CK_M / 128, 2), 256>>>(ow, nullptr, nullptr, nullptr, ob, out);
}

// round 16
// speedup vs baseline: 1.0027x; 1.0027x over previous
#include <cuda_runtime.h>
#include <cstdint>

#define CK_NSEQ 128
#define CK_NRES 256
#define CK_D    256
#define CK_P    128
#define CK_H    8
#define CK_C    32
#define CK_M    (CK_NSEQ * CK_NRES)   // 32768 rows

// ---------------------------------------------------------------------------
// Scratch (device globals -- no allocation allowed in kernel_launch)
// ---------------------------------------------------------------------------
__device__ float g_x   [CK_M * CK_D];            // LN(msa), tf32-rounded
__device__ float g_q   [CK_M * CK_D];            // [b,h,r,c], scaled, tf32
__device__ float g_k   [CK_M * CK_D];            // [b,h,r,c], tf32
__device__ float g_v   [CK_M * CK_D];            // [b,h,r,c], tf32
__device__ float g_gate[CK_M * CK_D];            // [b,r,h*c], sigmoid(.)
__device__ float g_o   [CK_M * CK_D];            // [b,r,h*c], gated attn out, tf32
__device__ float g_bias[CK_H * CK_NRES * CK_NRES]; // [h,q,k]

// ---------------------------------------------------------------------------
// Helpers
// ---------------------------------------------------------------------------
__device__ __forceinline__ float tf32r(float x) {
    unsigned u;
    asm("cvt.rna.tf32.f32 %0, %1;" : "=r"(u) : "f"(x));
    return __uint_as_float(u);
}
__device__ __forceinline__ unsigned fbits(float x) { return __float_as_uint(x); }

__device__ __forceinline__ void mma_tf32(float c[4], const unsigned a[4], const unsigned b[2]) {
    asm volatile(
        "mma.sync.aligned.m16n8k8.row.col.f32.tf32.tf32.f32 "
        "{%0,%1,%2,%3}, {%4,%5,%6,%7}, {%8,%9}, {%0,%1,%2,%3};"
        : "+f"(c[0]), "+f"(c[1]), "+f"(c[2]), "+f"(c[3])
        : "r"(a[0]), "r"(a[1]), "r"(a[2]), "r"(a[3]), "r"(b[0]), "r"(b[1]));
}

// ---------------------------------------------------------------------------
// Kernel A: LayerNorm over msa_act last dim (256). One block per row.
// ---------------------------------------------------------------------------
__global__ void __launch_bounds__(256) ln_msa_kernel(
    const float* __restrict__ x, const float* __restrict__ sc, const float* __restrict__ bi)
{
    const int row  = blockIdx.x;
    const int tid  = threadIdx.x;
    const int lane = tid & 31, w = tid >> 5;

    float v  = x[(size_t)row * 256 + tid];
    float s  = v, ss = v * v;
    #pragma unroll
    for (int off = 16; off > 0; off >>= 1) {
        s  += __shfl_xor_sync(0xffffffffu, s,  off);
        ss += __shfl_xor_sync(0xffffffffu, ss, off);
    }
    __shared__ float sm[16];
    if (lane == 0) { sm[w] = s; sm[8 + w] = ss; }
    __syncthreads();
    float tot = 0.f, tot2 = 0.f;
    #pragma unroll
    for (int i = 0; i < 8; i++) { tot += sm[i]; tot2 += sm[8 + i]; }
    float mu  = tot * (1.0f / 256.0f);
    float var = tot2 * (1.0f / 256.0f) - mu * mu;
    float rs  = rsqrtf(var + 1e-5f);
    g_x[(size_t)row * 256 + tid] = tf32r((v - mu) * rs * sc[tid] + bi[tid]);
}

// ---------------------------------------------------------------------------
// Kernel B: LN(pair) fused with bias[h,q,k] = sum_c pnorm[q,k,c] * feat2d_w[c,h].
// One warp per (q,k) pair; 128 channels = 4 per lane.
// ---------------------------------------------------------------------------
__global__ void __launch_bounds__(256) pair_bias_kernel(
    const float* __restrict__ pair, const float* __restrict__ ps,
    const float* __restrict__ pb,   const float* __restrict__ f2w)
{
    const int wg   = blockIdx.x * 8 + (threadIdx.x >> 5);
    const int lane = threadIdx.x & 31;
    const int q = wg >> 8, k = wg & 255;

    float4 v = reinterpret_cast<const float4*>(pair + (size_t)(q * 256 + k) * 128)[lane];
    float s  = v.x + v.y + v.z + v.w;
    float ss = v.x * v.x + v.y * v.y + v.z * v.z + v.w * v.w;
    #pragma unroll
    for (int off = 16; off > 0; off >>= 1) {
        s  += __shfl_xor_sync(0xffffffffu, s,  off);
        ss += __shfl_xor_sync(0xffffffffu, ss, off);
    }
    float mu  = s * (1.0f / 128.0f);
    float var = ss * (1.0f / 128.0f) - mu * mu;
    float rs  = rsqrtf(var + 1e-5f);

    float4 scv = reinterpret_cast<const float4*>(ps)[lane];
    float4 biv = reinterpret_cast<const float4*>(pb)[lane];
    float nv[4];
    nv[0] = (v.x - mu) * rs * scv.x + biv.x;
    nv[1] = (v.y - mu) * rs * scv.y + biv.y;
    nv[2] = (v.z - mu) * rs * scv.z + biv.z;
    nv[3] = (v.w - mu) * rs * scv.w + biv.w;

    float part[8] = {0, 0, 0, 0, 0, 0, 0, 0};
    const int c0 = lane * 4;
    #pragma unroll
    for (int j = 0; j < 4; j++) {
        const float* wr = f2w + (size_t)(c0 + j) * 8;
        float4 wa = reinterpret_cast<const float4*>(wr)[0];
        float4 wb = reinterpret_cast<const float4*>(wr)[1];
        float nj = nv[j];
        part[0] += nj * wa.x; part[1] += nj * wa.y; part[2] += nj * wa.z; part[3] += nj * wa.w;
        part[4] += nj * wb.x; part[5] += nj * wb.y; part[6] += nj * wb.z; part[7] += nj * wb.w;
    }
    #pragma unroll
    for (int hh = 0; hh < 8; hh++)
        #pragma unroll
        for (int off = 16; off > 0; off >>= 1)
            part[hh] += __shfl_xor_sync(0xffffffffu, part[hh], off);

    if (lane == 0) {
        #pragma unroll
        for (int hh = 0; hh < 8; hh++)
            g_bias[(size_t)hh * (CK_NRES * CK_NRES) + q * 256 + k] = part[hh];
    }
}

// ---------------------------------------------------------------------------
// GEMM (tf32 mma.sync m16n8k8): C[M,Ncols] = A[M,256] * W[256,Ncols]
// Block tile 128x128, BK=16, 8 warps (4x2), warp tile 32x64.
// MODE 0: A = g_x, four weight segments (Q,K,V,Gate) with custom epilogues.
// MODE 1: A = g_o, W = o_w, epilogue adds o_b and writes d_out.
// ---------------------------------------------------------------------------
template <int MODE>
__global__ void __launch_bounds__(256) gemm_kernel(
    const float* __restrict__ W0, const float* __restrict__ W1,
    const float* __restrict__ W2, const float* __restrict__ W3,
    const float* __restrict__ bias, float* __restrict__ out)
{
    const int bm = blockIdx.x, bn = blockIdx.y;
    const int tid = threadIdx.x;
    const int w = tid >> 5, lane = tid & 31;
    const int g = lane >> 2, t = lane & 3;
    const int wm = w >> 1, wn = w & 1;

    const float* A = (MODE == 0) ? g_x : g_o;
    const float* Bp;
    if (MODE == 0) {
        const int seg = bn >> 1;
        Bp = (seg == 0 ? W0 : seg == 1 ? W1 : seg == 2 ? W2 : W3) + (bn & 1) * 128;
    } else {
        Bp = W0 + bn * 128;
    }

    __shared__ float As[16][132];
    __shared__ float Bs[16][132];

    float c[2][8][4];
    #pragma unroll
    for (int i = 0; i < 2; i++)
        #pragma unroll
        for (int j = 0; j < 8; j++)
            #pragma unroll
            for (int r = 0; r < 4; r++) c[i][j][r] = 0.f;

    for (int kt = 0; kt < 16; ++kt) {
        const int k0 = kt * 16;
        #pragma unroll
        for (int i = 0; i < 2; i++) {
            int idx = tid + i * 256;
            int row = idx >> 2, f4 = idx & 3;
            float4 v = *reinterpret_cast<const float4*>(
                A + (size_t)(bm * 128 + row) * 256 + k0 + f4 * 4);
            As[f4 * 4 + 0][row] = v.x; As[f4 * 4 + 1][row] = v.y;
            As[f4 * 4 + 2][row] = v.z; As[f4 * 4 + 3][row] = v.w;
        }
        #pragma unroll
        for (int i = 0; i < 2; i++) {
            int idx = tid + i * 256;
            int row = idx >> 5, fc = idx & 31;
            float4 v = *reinterpret_cast<const float4*>(
                Bp + (size_t)(k0 + row) * 256 + fc * 4);
            Bs[row][fc * 4 + 0] = tf32r(v.x); Bs[row][fc * 4 + 1] = tf32r(v.y);
            Bs[row][fc * 4 + 2] = tf32r(v.z); Bs[row][fc * 4 + 3] = tf32r(v.w);
        }
        __syncthreads();

        #pragma unroll
        for (int ks = 0; ks < 2; ks++) {
            const int kk = ks * 8;
            unsigned a[2][4], bfr[8][2];
            #pragma unroll
            for (int mt = 0; mt < 2; mt++) {
                int m0 = wm * 32 + mt * 16 + g;
                a[mt][0] = fbits(As[kk + t][m0]);
                a[mt][1] = fbits(As[kk + t][m0 + 8]);
                a[mt][2] = fbits(As[kk + t + 4][m0]);
                a[mt][3] = fbits(As[kk + t + 4][m0 + 8]);
            }
            #pragma unroll
            for (int nt = 0; nt < 8; nt++) {
                int n0 = wn * 64 + nt * 8 + g;
                bfr[nt][0] = fbits(Bs[kk + t][n0]);
                bfr[nt][1] = fbits(Bs[kk + t + 4][n0]);
            }
            #pragma unroll
            for (int mt = 0; mt < 2; mt++)
                #pragma unroll
                for (int nt = 0; nt < 8; nt++)
                    mma_tf32(c[mt][nt], a[mt], bfr[nt]);
        }
        __syncthreads();
    }

    // Epilogue
    #pragma unroll
    for (int mt = 0; mt < 2; mt++)
        #pragma unroll
        for (int r2 = 0; r2 < 2; r2++) {
            const int grow = bm * 128 + wm * 32 + mt * 16 + r2 * 8 + g;
            const int b = grow >> 8, qr = grow & 255;
            #pragma unroll
            for (int nt = 0; nt < 8; nt++)
                #pragma unroll
                for (int j = 0; j < 2; j++) {
                    float val = c[mt][nt][r2 * 2 + j];
                    const int lcol = wn * 64 + nt * 8 + 2 * t + j;
                    if (MODE == 0) {
                        const int segcol = (bn & 1) * 128 + lcol;
                        const int seg = bn >> 1;
                        const int h = segcol >> 5, cc = segcol & 31;
                        const size_t qidx =
                            ((size_t)((b * CK_H + h) * CK_NRES + qr)) * CK_C + cc;
                        if (seg == 0)      g_q[qidx] = tf32r(val * 0.17677669529663687f);
                        else if (seg == 1) g_k[qidx] = tf32r(val);
                        else if (seg == 2) g_v[qidx] = tf32r(val);
                        else {
                            float z = val + bias[segcol];
                            g_gate[(size_t)grow * 256 + segcol] = 1.0f / (1.0f + __expf(-z));
                        }
                    } else {
                        const int gcol = bn * 128 + lcol;
                        out[(size_t)grow * 256 + gcol] = val + bias[gcol];
                    }
                }
        }
}

// ---------------------------------------------------------------------------
// Kernel D: attention per (b,h). 8 warps x 32 q-rows. Flash-style over K
// chunks of 64. S held in mma accumulators; P transposed C->A fragments via
// register shuffles (no smem round trip). Gating fused into epilogue.
// ---------------------------------------------------------------------------
__global__ void __launch_bounds__(256) attn_kernel(const float* __restrict__ mask)
{
    const int b = blockIdx.x, h = blockIdx.y;
    const int tid = threadIdx.x;
    const int lane = tid & 31, w = tid >> 5;
    const int g = lane >> 2, t = lane & 3;

    alignas(16) __shared__ float Ks[64][36];
    alignas(16) __shared__ float Vs[64][36];
    __shared__ float ms[256];

    ms[tid] = 1e9f * (mask[(size_t)b * 256 + tid] - 1.0f);

    const size_t bh = (size_t)(b * CK_H + h) * CK_NRES * CK_C;
    const float* Qb = g_q + bh;
    const float* Kb = g_k + bh;
    const float* Vb = g_v + bh;
    const float* biasb = g_bias + (size_t)h * (CK_NRES * CK_NRES);

    const int q0 = w * 32;

    // Q fragments (rows q0..q0+31, cols 0..31), held for all chunks
    unsigned aq[4][2][4];
    #pragma unroll
    for (int ks = 0; ks < 4; ks++)
        #pragma unroll
        for (int mt = 0; mt < 2; mt++) {
            int r0 = q0 + mt * 16 + g;
            aq[ks][mt][0] = fbits(Qb[(size_t)r0 * 32 + ks * 8 + t]);
            aq[ks][mt][1] = fbits(Qb[(size_t)(r0 + 8) * 32 + ks * 8 + t]);
            aq[ks][mt][2] = fbits(Qb[(size_t)r0 * 32 + ks * 8 + t + 4]);
            aq[ks][mt][3] = fbits(Qb[(size_t)(r0 + 8) * 32 + ks * 8 + t + 4]);
        }

    float o[2][4][4];
    #pragma unroll
    for (int i = 0; i < 2; i++)
        #pragma unroll
        for (int j = 0; j < 4; j++)
            #pragma unroll
            for (int r = 0; r < 4; r++) o[i][j][r] = 0.f;
    float mrow[2][2] = {{-1e30f, -1e30f}, {-1e30f, -1e30f}};
    float lrow[2][2] = {{0.f, 0.f}, {0.f, 0.f}};

    for (int ch = 0; ch < 4; ch++) {
        const int kb = ch * 64;
        __syncthreads();
        #pragma unroll
        for (int i = 0; i < 2; i++) {
            int idx = tid + i * 256;
            int row = idx >> 3, f4 = idx & 7;
            float4 kv = *reinterpret_cast<const float4*>(Kb + (size_t)(kb + row) * 32 + f4 * 4);
            *reinterpret_cast<float4*>(&Ks[row][f4 * 4]) = kv;
            float4 vv = *reinterpret_cast<const float4*>(Vb + (size_t)(kb + row) * 32 + f4 * 4);
            *reinterpret_cast<float4*>(&Vs[row][f4 * 4]) = vv;
        }
        __syncthreads();

        // S = Q * K^T (chunk 32 x 64)
        float s[2][8][4];
        #pragma unroll
        for (int i = 0; i < 2; i++)
            #pragma unroll
            for (int j = 0; j < 8; j++)
                #pragma unroll
                for (int r = 0; r < 4; r++) s[i][j][r] = 0.f;

        #pragma unroll
        for (int ks = 0; ks < 4; ks++) {
            unsigned bk[8][2];
            #pragma unroll
            for (int nt = 0; nt < 8; nt++) {
                bk[nt][0] = fbits(Ks[nt * 8 + g][ks * 8 + t]);
                bk[nt][1] = fbits(Ks[nt * 8 + g][ks * 8 + t + 4]);
            }
            #pragma unroll
            for (int mt = 0; mt < 2; mt++)
                #pragma unroll
                for (int nt = 0; nt < 8; nt++)
                    mma_tf32(s[mt][nt], aq[ks][mt], bk[nt]);
        }

        // bias + mask + online softmax
        #pragma unroll
        for (int mt = 0; mt < 2; mt++)
            #pragma unroll
            for (int rh = 0; rh < 2; rh++) {
                const int qr = q0 + mt * 16 + rh * 8 + g;
                const float* brow = biasb + (size_t)qr * 256 + kb;
                float mx = -1e30f;
                #pragma unroll
                for (int nt = 0; nt < 8; nt++)
                    #pragma unroll
                    for (int j = 0; j < 2; j++) {
                        int kc = nt * 8 + 2 * t + j;
                        float x = s[mt][nt][rh * 2 + j] + brow[kc] + ms[kb + kc];
                        s[mt][nt][rh * 2 + j] = x;
                        mx = fmaxf(mx, x);
                    }
                mx = fmaxf(mx, __shfl_xor_sync(0xffffffffu, mx, 1));
                mx = fmaxf(mx, __shfl_xor_sync(0xffffffffu, mx, 2));
                float nm   = fmaxf(mrow[mt][rh], mx);
                float corr = __expf(mrow[mt][rh] - nm);
                mrow[mt][rh] = nm;
                float rs = 0.f;
                #pragma unroll
                for (int nt = 0; nt < 8; nt++)
                    #pragma unroll
                    for (int j = 0; j < 2; j++) {
                        float p = __expf(s[mt][nt][rh * 2 + j] - nm);
                        s[mt][nt][rh * 2 + j] = p;
                        rs += p;
                    }
                rs += __shfl_xor_sync(0xffffffffu, rs, 1);
                rs += __shfl_xor_sync(0xffffffffu, rs, 2);
                lrow[mt][rh] = lrow[mt][rh] * corr + rs;
                #pragma unroll
                for (int nt = 0; nt < 4; nt++)
                    #pragma unroll
                    for (int j = 0; j < 2; j++)
                        o[mt][nt][rh * 2 + j] *= corr;
            }

        // O += P * V   (P: C-fragment -> A-fragment via shuffles)
        const int srcbase = lane & ~3;
        const int src0 = srcbase | (t >> 1);
        const int src1 = srcbase | ((t >> 1) + 2);
        const bool odd = (t & 1);
        #pragma unroll
        for (int ks = 0; ks < 8; ks++) {
            unsigned bv[4][2];
            #pragma unroll
            for (int nt = 0; nt < 4; nt++) {
                bv[nt][0] = fbits(Vs[ks * 8 + t][nt * 8 + g]);
                bv[nt][1] = fbits(Vs[ks * 8 + t + 4][nt * 8 + g]);
            }
            #pragma unroll
            for (int mt = 0; mt < 2; mt++) {
                unsigned pa[4];
                float lo, hi;
                lo = __shfl_sync(0xffffffffu, s[mt][ks][0], src0);
                hi = __shfl_sync(0xffffffffu, s[mt][ks][1], src0);
                pa[0] = fbits(tf32r(odd ? hi : lo));
                lo = __shfl_sync(0xffffffffu, s[mt][ks][2], src0);
                hi = __shfl_sync(0xffffffffu, s[mt][ks][3], src0);
                pa[1] = fbits(tf32r(odd ? hi : lo));
                lo = __shfl_sync(0xffffffffu, s[mt][ks][0], src1);
                hi = __shfl_sync(0xffffffffu, s[mt][ks][1], src1);
                pa[2] = fbits(tf32r(odd ? hi : lo));
                lo = __shfl_sync(0xffffffffu, s[mt][ks][2], src1);
                hi = __shfl_sync(0xffffffffu, s[mt][ks][3], src1);
                pa[3] = fbits(tf32r(odd ? hi : lo));
                #pragma unroll
                for (int nt = 0; nt < 4; nt++)
                    mma_tf32(o[mt][nt], pa, bv[nt]);
            }
        }
    }

    // finalize: normalize, gate, store (tf32-rounded for the output GEMM)
    #pragma unroll
    for (int mt = 0; mt < 2; mt++)
        #pragma unroll
        for (int rh = 0; rh < 2; rh++) {
            const float inv = 1.0f / lrow[mt][rh];
            const int qr = q0 + mt * 16 + rh * 8 + g;
            const size_t rowoff = ((size_t)(b * CK_NRES + qr)) * CK_D + h * CK_C;
            const float* gp = g_gate + rowoff;
            float* op = g_o + rowoff;
            #pragma unroll
            for (int nt = 0; nt < 4; nt++)
                #pragma unroll
                for (int j = 0; j < 2; j++) {
                    int cc = nt * 8 + 2 * t + j;
                    op[cc] = tf32r(o[mt][nt][rh * 2 + j] * inv * gp[cc]);
                }
        }
}

// ---------------------------------------------------------------------------
// Launch
// ---------------------------------------------------------------------------
extern "C" void kernel_launch(void* const* d_in, const int* in_sizes, int n_in,
                              void* d_out, int out_size)
{
    const float* msa  = (const float*)d_in[0];
    const float* mask = (const float*)d_in[1];
    const float* pair = (const float*)d_in[2];
    const float* qns  = (const float*)d_in[3];
    const float* qnb  = (const float*)d_in[4];
    const float* pns  = (const float*)d_in[5];
    const float* pnb  = (const float*)d_in[6];
    const float* f2w  = (const float*)d_in[7];
    const float* qw   = (const float*)d_in[8];
    const float* kw   = (const float*)d_in[9];
    const float* vw   = (const float*)d_in[10];
    const float* gw   = (const float*)d_in[11];
    const float* gatb = (const float*)d_in[12];
    const float* ow   = (const float*)d_in[13];
    const float* ob   = (const float*)d_in[14];
    float* out = (float*)d_out;

    ln_msa_kernel<<<CK_M, 256>>>(msa, qns, qnb);
    pair_bias_kernel<<<(CK_NRES * CK_NRES) / 8, 256>>>(pair, pns, pnb, f2w);
    gemm_kernel<0><<<dim3(CK_M / 128, 8), 256>>>(qw, kw, vw, gw, gatb, nullptr);
    attn_kernel<<<dim3(CK_NSEQ, CK_H), 256>>>(mask);
    gemm_kernel<1><<<dim3(CK_M / 128, 2), 256>>>(ow, nullptr, nullptr, nullptr, ob, out);
}